// round 15
// baseline (speedup 1.0000x reference)
#include <cuda_runtime.h>
#include <cuda_bf16.h>
#include <math.h>
#include <stdint.h>

#define NJ 33
#define FD 256
#define MAXB 4096
#define NNMAX (MAXB*NJ)
#define MAXE 165

typedef uint32_t u32;
typedef uint64_t u64;

// ---- scratch (no allocations allowed) ----
__device__ float g_bufA[(size_t)NNMAX*FD];
__device__ float g_sum[FD], g_sumsq[FD];
__device__ float g_scale[FD], g_shift[FD];
__device__ int   g_rp[NJ+1];
__device__ int   g_ci[MAXE];
__device__ float g_av[MAXE];
__device__ float g_acol[NJ];
__device__ float g_whc[FD*4];
__device__ float g_bhc[4];
// Weights pre-packed in m16n8k16 B-fragment order, bf16 hi/lo split.
__device__ u64 g_wb_hi[3][16384];
__device__ u64 g_wb_lo[3][16384];

__device__ __forceinline__ u32 smem_u32(const void* p) {
    u32 a;
    asm("{ .reg .u64 t; cvta.to.shared.u64 t, %1; cvt.u32.u64 %0, t; }" : "=r"(a) : "l"(p));
    return a;
}
__device__ __forceinline__ void ldsm_x4(u32* r, u32 addr) {
    asm volatile("ldmatrix.sync.aligned.m8n8.x4.shared.b16 {%0,%1,%2,%3}, [%4];"
        : "=r"(r[0]), "=r"(r[1]), "=r"(r[2]), "=r"(r[3]) : "r"(addr));
}

// ============================================================
// Prep (parallelized CSR build)
// ============================================================
__global__ void prep_kernel(const int* __restrict__ src, const int* __restrict__ dst,
                            int epg,
                            const float* __restrict__ wh, const float* __restrict__ wc,
                            const float* __restrict__ bh, const float* __restrict__ bc) {
    __shared__ int   s_s[MAXE], s_d[MAXE];
    __shared__ float s_dinv[NJ];
    __shared__ int   s_cnt[NJ];
    const int tid = threadIdx.x;
    if (tid < epg && tid < MAXE) { s_s[tid] = src[tid]; s_d[tid] = dst[tid]; }
    if (tid < FD) { g_sum[tid] = 0.f; g_sumsq[tid] = 0.f; }
    __syncthreads();
    if (tid < NJ) {
        int d = 0;
        for (int e = 0; e < epg; ++e) d += (s_d[e] == tid);
        s_cnt[tid] = d;
        s_dinv[tid] = rsqrtf((float)d);
    }
    __syncthreads();
    if (tid == 0) {
        int pos = 0;
        for (int j = 0; j < NJ; ++j) { g_rp[j] = pos; pos += s_cnt[j]; }
        g_rp[NJ] = pos;
    }
    __syncthreads();
    if (tid < NJ) {
        int pos = g_rp[tid];
        float s = 0.f;
        for (int e = 0; e < epg; ++e) {
            if (s_d[e] == tid) {
                const int r = s_s[e];
                g_ci[pos] = r;
                g_av[pos] = s_dinv[r] * s_dinv[tid];
                pos++;
            }
            if (s_s[e] == tid) s += s_dinv[tid] * s_dinv[s_d[e]];
        }
        g_acol[tid] = s / (float)NJ;
    }
    for (int idx = tid; idx < FD*4; idx += blockDim.x) {
        int k = idx >> 2, l = idx & 3;
        float s = 0.f;
        for (int c = 0; c < FD; ++c) s += wh[k*FD + c] * wc[c*4 + l];
        g_whc[idx] = s;
    }
    if (tid < 4) {
        float s = 0.f;
        for (int c = 0; c < FD; ++c) s += bh[c] * wc[c*4 + tid];
        g_bhc[tid] = s + bc[tid];
    }
}

// W[k][n] fp32 -> fragment-ordered bf16 hi/lo pack.
__global__ void convw_kernel(const float* __restrict__ W, int layer) {
    const int i = blockIdx.x * 256 + threadIdx.x;       // 0..16383
    const int lane = i & 31;
    const int ks = (i >> 5) & 15;
    const int nf = i >> 9;
    const int n = nf*8 + (lane >> 2);
    const int k = ks*16 + (lane & 3)*2;
    float e0 = W[k*FD + n],     e1 = W[(k+1)*FD + n];
    float e2 = W[(k+8)*FD + n], e3 = W[(k+9)*FD + n];
    __nv_bfloat162 h0 = __floats2bfloat162_rn(e0, e1);
    __nv_bfloat162 h1 = __floats2bfloat162_rn(e2, e3);
    __nv_bfloat162 l0 = __floats2bfloat162_rn(e0 - __low2float(h0), e1 - __high2float(h0));
    __nv_bfloat162 l1 = __floats2bfloat162_rn(e2 - __low2float(h1), e3 - __high2float(h1));
    g_wb_hi[layer][i] = (u64)(*(u32*)&h0) | ((u64)(*(u32*)&h1) << 32);
    g_wb_lo[layer][i] = (u64)(*(u32*)&l0) | ((u64)(*(u32*)&l1) << 32);
}

// ============================================================
// Fully fused layer: pre(Z) @ W  then  A_hat @ Y + b, BN sums.
// Graph-major [g][j][f]: block = 4 graphs = 132 rows (pad 144).
// 16 warps = 2m x 8n: warps 0-7 own m-tiles 0-4, warps 8-15 own
// m-tiles 5-8; each warp n-stripe is 32 cols (4 n8 frags).
// A fragments via ldmatrix.x4 (row = lane&15, k-half = lane>>4);
// ASTRIDE=272 makes the 8-row phases conflict-free.
// ============================================================
#define ASTRIDE 272
#define A_HI 0
#define A_LO 39168          /* 144*272 */
#define SM_SC 147456        /* ybuf occupies [0,147456) after MMA */
#define SM_SH 148480
#define SM_RP 149504
#define SM_CI 149664
#define SM_AV 150328
#define FUSED_SMEM 151040

__device__ __forceinline__ void mma16816(float* d, u32 a0, u32 a1, u32 a2, u32 a3,
                                         u32 b0, u32 b1) {
    asm volatile(
        "mma.sync.aligned.m16n8k16.row.col.f32.bf16.bf16.f32 "
        "{%0,%1,%2,%3}, {%4,%5,%6,%7}, {%8,%9}, {%0,%1,%2,%3};"
        : "+f"(d[0]), "+f"(d[1]), "+f"(d[2]), "+f"(d[3])
        : "r"(a0), "r"(a1), "r"(a2), "r"(a3), "r"(b0), "r"(b1));
}

__global__ void __launch_bounds__(512)
fused_kernel(const float* __restrict__ x_ext, const float* __restrict__ bias,
             int in_sel /*0 = x + nan_to_num, 1 = g_bufA + BN+relu*/,
             int layer, int Bn) {
    extern __shared__ char smem[];
    const int tid  = threadIdx.x;
    const int lane = tid & 31, wid = tid >> 5;     // 16 warps
    const int wm   = wid >> 3;                      // m half: 0 -> mf 0-4, 1 -> mf 5-8
    const int wn   = wid & 7;                       // n stripe: cols [wn*32, wn*32+32)
    const int mf0  = wm ? 5 : 0;
    const int nmf  = wm ? 4 : 5;
    const int blk  = blockIdx.x;
    const int m0   = blk * 132;                     // global row base (graph-major)
    const int NNv  = Bn * NJ;
    const int mode = in_sel;

    const float* in = (in_sel == 0) ? x_ext : (const float*)g_bufA;

    // stage BN params + CSR into smem (regions above ybuf; persist whole kernel)
    if (tid < 256) {
        *(float*)(smem + SM_SC + tid*4) = g_scale[tid];
        *(float*)(smem + SM_SH + tid*4) = g_shift[tid];
    }
    if (tid <= NJ) *(int*)(smem + SM_RP + tid*4) = g_rp[tid];
    if (tid < MAXE) {
        *(int*)  (smem + SM_CI + tid*4) = g_ci[tid];
        *(float*)(smem + SM_AV + tid*4) = g_av[tid];
    }

    float acc[5][4][4];
    #pragma unroll
    for (int mi = 0; mi < 5; ++mi)
        #pragma unroll
        for (int nf = 0; nf < 4; ++nf)
            #pragma unroll
            for (int q = 0; q < 4; ++q) acc[mi][nf][q] = 0.f;

    const u64* __restrict__ WBH = g_wb_hi[layer];
    const u64* __restrict__ WBL = g_wb_lo[layer];

    const int rowl = tid >> 2, qc = tid & 3;        // loader: 128 rows x 4 quarters
    const float* ssc = (const float*)(smem + SM_SC);
    const float* ssh = (const float*)(smem + SM_SH);

    // ldmatrix lane address base: row = lane&15, k-half = lane>>4
    const u32 sbase = smem_u32(smem);
    const u32 lmbase = sbase + (u32)((mf0*16 + (lane & 15))*ASTRIDE + (lane >> 4)*16);

    const int arowb = (lane >> 2);                  // for Y staging

    for (int c = 0; c < 2; ++c) {
        __syncthreads();
        // ---- stage A: rows 0..143 (132 valid), k in [c*128, +128) ----
        #pragma unroll
        for (int rr = 0; rr < 2; ++rr) {
            const int r = rowl + rr*128;
            if (rr == 1 && rowl >= 16) break;
            const bool ok = (r < 132) && (m0 + r < NNv);
            char* hib = smem + A_HI + r*ASTRIDE + qc*64;
            char* lob = smem + A_LO + r*ASTRIDE + qc*64;
            const float* srcrow = in + (size_t)(m0 + r) * FD;
            #pragma unroll
            for (int i = 0; i < 8; ++i) {
                const int k = c*128 + qc*32 + i*4;
                float4 v = make_float4(0.f, 0.f, 0.f, 0.f);
                if (ok) {
                    v = *(const float4*)(srcrow + k);
                    if (mode == 0) {
                        if (v.x != v.x) v.x = 0.f;
                        if (v.y != v.y) v.y = 0.f;
                        if (v.z != v.z) v.z = 0.f;
                        if (v.w != v.w) v.w = 0.f;
                    } else {
                        v.x = fmaxf(fmaf(v.x, ssc[k],   ssh[k]),   0.f);
                        v.y = fmaxf(fmaf(v.y, ssc[k+1], ssh[k+1]), 0.f);
                        v.z = fmaxf(fmaf(v.z, ssc[k+2], ssh[k+2]), 0.f);
                        v.w = fmaxf(fmaf(v.w, ssc[k+3], ssh[k+3]), 0.f);
                    }
                }
                __nv_bfloat162 h0 = __floats2bfloat162_rn(v.x, v.y);
                __nv_bfloat162 h1 = __floats2bfloat162_rn(v.z, v.w);
                __nv_bfloat162 l0 = __floats2bfloat162_rn(v.x - __low2float(h0), v.y - __high2float(h0));
                __nv_bfloat162 l1 = __floats2bfloat162_rn(v.z - __low2float(h1), v.w - __high2float(h1));
                *(u32*)(hib + i*8)     = *(u32*)&h0;
                *(u32*)(hib + i*8 + 4) = *(u32*)&h1;
                *(u32*)(lob + i*8)     = *(u32*)&l0;
                *(u32*)(lob + i*8 + 4) = *(u32*)&l1;
            }
        }
        __syncthreads();

        for (int ks = 0; ks < 8; ++ks) {
            const int ksa = c*8 + ks;
            // B fragments (L2-resident LDG.64, warp-coalesced)
            u64 vh[4], vl[4];
            #pragma unroll
            for (int nf = 0; nf < 4; ++nf) {
                const int idx = ((wn*4 + nf)*16 + ksa)*32 + lane;
                vh[nf] = WBH[idx];
                vl[nf] = WBL[idx];
            }
            const u32 kadd = (u32)(ks*32);
            // process m-tiles in pairs: 8 independent MMAs between acc reuses
            #pragma unroll
            for (int mp = 0; mp < 3; ++mp) {
                const int mA = 2*mp, mB = 2*mp + 1;
                if (mA >= nmf) break;
                const bool hB = (mB < nmf);
                u32 AH0[4], AL0[4], AH1[4], AL1[4];
                {
                    const u32 a0 = lmbase + (u32)(mA*16*ASTRIDE) + kadd;
                    ldsm_x4(AH0, a0);
                    ldsm_x4(AL0, a0 + (u32)A_LO);
                }
                if (hB) {
                    const u32 a1 = lmbase + (u32)(mB*16*ASTRIDE) + kadd;
                    ldsm_x4(AH1, a1);
                    ldsm_x4(AL1, a1 + (u32)A_LO);
                }
                // term 1: hi * b_hi
                #pragma unroll
                for (int nf = 0; nf < 4; ++nf)
                    mma16816(acc[mA][nf], AH0[0], AH0[1], AH0[2], AH0[3], (u32)vh[nf], (u32)(vh[nf] >> 32));
                if (hB) {
                    #pragma unroll
                    for (int nf = 0; nf < 4; ++nf)
                        mma16816(acc[mB][nf], AH1[0], AH1[1], AH1[2], AH1[3], (u32)vh[nf], (u32)(vh[nf] >> 32));
                }
                // term 2: hi * b_lo
                #pragma unroll
                for (int nf = 0; nf < 4; ++nf)
                    mma16816(acc[mA][nf], AH0[0], AH0[1], AH0[2], AH0[3], (u32)vl[nf], (u32)(vl[nf] >> 32));
                if (hB) {
                    #pragma unroll
                    for (int nf = 0; nf < 4; ++nf)
                        mma16816(acc[mB][nf], AH1[0], AH1[1], AH1[2], AH1[3], (u32)vl[nf], (u32)(vl[nf] >> 32));
                }
                // term 3: lo * b_hi
                #pragma unroll
                for (int nf = 0; nf < 4; ++nf)
                    mma16816(acc[mA][nf], AL0[0], AL0[1], AL0[2], AL0[3], (u32)vh[nf], (u32)(vh[nf] >> 32));
                if (hB) {
                    #pragma unroll
                    for (int nf = 0; nf < 4; ++nf)
                        mma16816(acc[mB][nf], AL1[0], AL1[1], AL1[2], AL1[3], (u32)vh[nf], (u32)(vh[nf] >> 32));
                }
            }
        }
    }

    // ---- stage Y into smem (overwrites A region) ----
    __syncthreads();
    float2* yb = (float2*)smem;                     // [row*128 + colpair], 144 rows
    const int cpb = wn*16 + (lane & 3);
    #pragma unroll
    for (int mi = 0; mi < 5; ++mi) {
        if (mi >= nmf) break;
        const int r0 = (mf0 + mi)*16 + arowb;
        #pragma unroll
        for (int nf = 0; nf < 4; ++nf) {
            const int cpi = cpb + nf*4;
            yb[ r0     *128 + cpi] = make_float2(acc[mi][nf][0], acc[mi][nf][1]);
            yb[(r0 + 8)*128 + cpi] = make_float2(acc[mi][nf][2], acc[mi][nf][3]);
        }
    }
    __syncthreads();

    // ---- sparse A_hat epilogue + bias + BN sums ----
    const int cp = tid & 127, gi = tid >> 7;        // 4 graphs, 128 col-pairs
    const int g0 = blk*4 + gi;
    if (g0 < Bn) {
        const int*   srp = (const int*)(smem + SM_RP);
        const int*   sci = (const int*)(smem + SM_CI);
        const float* sav = (const float*)(smem + SM_AV);
        const float2 bia = ((const float2*)bias)[cp];
        float s1x = 0.f, s1y = 0.f, s2x = 0.f, s2y = 0.f;
        float* outg = g_bufA + (size_t)(m0 + gi*NJ) * FD;
        for (int j = 0; j < NJ; ++j) {
            float zx = bia.x, zy = bia.y;
            const int p1 = srp[j+1];
            for (int p = srp[j]; p < p1; ++p) {
                const float  a = sav[p];
                const float2 y = yb[(gi*NJ + sci[p])*128 + cp];
                zx = fmaf(a, y.x, zx);
                zy = fmaf(a, y.y, zy);
            }
            *(float2*)(outg + j*FD + cp*2) = make_float2(zx, zy);
            s1x += zx; s1y += zy;
            s2x = fmaf(zx, zx, s2x); s2y = fmaf(zy, zy, s2y);
        }
        atomicAdd(&g_sum[2*cp],     s1x);
        atomicAdd(&g_sum[2*cp + 1], s1y);
        atomicAdd(&g_sumsq[2*cp],     s2x);
        atomicAdd(&g_sumsq[2*cp + 1], s2y);
    }
}

// ============================================================
__global__ void stats_kernel(const float* __restrict__ g, const float* __restrict__ be,
                             float inv_nn) {
    int tid = threadIdx.x;
    float mu  = g_sum[tid] * inv_nn;
    float var = g_sumsq[tid] * inv_nn - mu * mu;
    float rs  = rsqrtf(var + 1e-5f);
    float sc  = rs * g[tid];
    g_scale[tid] = sc;
    g_shift[tid] = be[tid] - mu * sc;
    g_sum[tid] = 0.f; g_sumsq[tid] = 0.f;
}

// ============================================================
// Head: BN2+ReLU -> a_col^T h (per graph, graph-major) -> whc + bhc
// ============================================================
__global__ void __launch_bounds__(256)
final_kernel(float* __restrict__ out, int Bn) {
    __shared__ float s_acol[NJ];
    __shared__ float s_red[8][4];
    const int tid = threadIdx.x;
    const int b   = blockIdx.x;
    if (tid < NJ) s_acol[tid] = g_acol[tid];
    __syncthreads();

    const float sc  = g_scale[tid];
    const float shf = g_shift[tid];
    const float* inb = g_bufA + (size_t)b * NJ * FD;

    float v = 0.f;
    #pragma unroll
    for (int r = 0; r < NJ; ++r) {
        float x = inb[r*FD + tid];
        x = fmaxf(fmaf(x, sc, shf), 0.f);
        v = fmaf(s_acol[r], x, v);
    }
    float4 w = ((const float4*)g_whc)[tid];
    float p0 = v * w.x, p1 = v * w.y, p2 = v * w.z, p3 = v * w.w;
    #pragma unroll
    for (int o = 16; o; o >>= 1) {
        p0 += __shfl_down_sync(0xffffffffu, p0, o);
        p1 += __shfl_down_sync(0xffffffffu, p1, o);
        p2 += __shfl_down_sync(0xffffffffu, p2, o);
        p3 += __shfl_down_sync(0xffffffffu, p3, o);
    }
    const int lane = tid & 31, wid = tid >> 5;
    if (lane == 0) { s_red[wid][0] = p0; s_red[wid][1] = p1; s_red[wid][2] = p2; s_red[wid][3] = p3; }
    __syncthreads();
    if (tid < 4) {
        float s = 0.f;
        #pragma unroll
        for (int w8 = 0; w8 < 8; ++w8) s += s_red[w8][tid];
        out[b*4 + tid] = s + g_bhc[tid];
    }
}

// ============================================================
extern "C" void kernel_launch(void* const* d_in, const int* in_sizes, int n_in,
                              void* d_out, int out_size) {
    const float* x   = (const float*)d_in[0];
    const float* w0  = (const float*)d_in[1];
    const float* b0  = (const float*)d_in[2];
    const float* gg0 = (const float*)d_in[3];
    const float* be0 = (const float*)d_in[4];
    const float* w1  = (const float*)d_in[5];
    const float* b1  = (const float*)d_in[6];
    const float* gg1 = (const float*)d_in[7];
    const float* be1 = (const float*)d_in[8];
    const float* w2  = (const float*)d_in[9];
    const float* b2  = (const float*)d_in[10];
    const float* gg2 = (const float*)d_in[11];
    const float* be2 = (const float*)d_in[12];
    const float* wh  = (const float*)d_in[13];
    const float* bh  = (const float*)d_in[14];
    const float* wc  = (const float*)d_in[15];
    const float* bc  = (const float*)d_in[16];
    const int*   src = (const int*)d_in[17];
    const int*   dst = (const int*)d_in[18];
    float* out = (float*)d_out;

    const int B   = in_sizes[0] / (NJ * FD);
    const int epg = in_sizes[17] / B;
    const float inv_nn = 1.0f / (float)(B * NJ);
    const int fused_grid = (B + 3) / 4;

    static int smem_set = 0;
    if (!smem_set) {
        cudaFuncSetAttribute(fused_kernel, cudaFuncAttributeMaxDynamicSharedMemorySize, FUSED_SMEM);
        smem_set = 1;
    }

    // fused_kernel is launch #4 (ncu capture slot).
    prep_kernel<<<1, 256>>>(src, dst, epg, wh, wc, bh, bc);
    convw_kernel<<<64, 256>>>(w0, 0);
    convw_kernel<<<64, 256>>>(w1, 1);

    fused_kernel<<<fused_grid, 512, FUSED_SMEM>>>(x, b0, 0, 0, B);
    stats_kernel<<<1, 256>>>(gg0, be0, inv_nn);
    convw_kernel<<<64, 256>>>(w2, 2);

    fused_kernel<<<fused_grid, 512, FUSED_SMEM>>>(x, b1, 1, 1, B);
    stats_kernel<<<1, 256>>>(gg1, be1, inv_nn);

    fused_kernel<<<fused_grid, 512, FUSED_SMEM>>>(x, b2, 1, 2, B);
    stats_kernel<<<1, 256>>>(gg2, be2, inv_nn);

    final_kernel<<<B, 256>>>(out, B);
}

// round 16
// speedup vs baseline: 1.2624x; 1.2624x over previous
#include <cuda_runtime.h>
#include <cuda_bf16.h>
#include <math.h>
#include <stdint.h>

#define NJ 33
#define FD 256
#define MAXB 4096
#define NNMAX (MAXB*NJ)
#define MAXE 165

typedef uint32_t u32;
typedef uint64_t u64;

// ---- scratch (no allocations allowed) ----
__device__ float g_bufA[(size_t)NNMAX*FD];
__device__ float g_sum[FD], g_sumsq[FD];
__device__ float g_scale[FD], g_shift[FD];
__device__ int   g_rp[NJ+1];
__device__ int   g_ci[MAXE];
__device__ float g_av[MAXE];
__device__ float g_acol[NJ];
__device__ float g_whc[FD*4];
__device__ float g_bhc[4];
// Weights pre-packed in m16n8k16 B-fragment order, bf16 hi/lo split.
__device__ u64 g_wb_hi[3][16384];
__device__ u64 g_wb_lo[3][16384];

__device__ __forceinline__ u32 smem_u32(const void* p) {
    u32 a;
    asm("{ .reg .u64 t; cvta.to.shared.u64 t, %1; cvt.u32.u64 %0, t; }" : "=r"(a) : "l"(p));
    return a;
}
__device__ __forceinline__ void ldsm_x4(u32* r, u32 addr) {
    asm volatile("ldmatrix.sync.aligned.m8n8.x4.shared.b16 {%0,%1,%2,%3}, [%4];"
        : "=r"(r[0]), "=r"(r[1]), "=r"(r[2]), "=r"(r[3]) : "r"(addr));
}

// ============================================================
// Prep (parallelized CSR build)
// ============================================================
__global__ void prep_kernel(const int* __restrict__ src, const int* __restrict__ dst,
                            int epg,
                            const float* __restrict__ wh, const float* __restrict__ wc,
                            const float* __restrict__ bh, const float* __restrict__ bc) {
    __shared__ int   s_s[MAXE], s_d[MAXE];
    __shared__ float s_dinv[NJ];
    __shared__ int   s_cnt[NJ];
    const int tid = threadIdx.x;
    if (tid < epg && tid < MAXE) { s_s[tid] = src[tid]; s_d[tid] = dst[tid]; }
    if (tid < FD) { g_sum[tid] = 0.f; g_sumsq[tid] = 0.f; }
    __syncthreads();
    if (tid < NJ) {
        int d = 0;
        for (int e = 0; e < epg; ++e) d += (s_d[e] == tid);
        s_cnt[tid] = d;
        s_dinv[tid] = rsqrtf((float)d);
    }
    __syncthreads();
    if (tid == 0) {
        int pos = 0;
        for (int j = 0; j < NJ; ++j) { g_rp[j] = pos; pos += s_cnt[j]; }
        g_rp[NJ] = pos;
    }
    __syncthreads();
    if (tid < NJ) {
        int pos = g_rp[tid];
        float s = 0.f;
        for (int e = 0; e < epg; ++e) {
            if (s_d[e] == tid) {
                const int r = s_s[e];
                g_ci[pos] = r;
                g_av[pos] = s_dinv[r] * s_dinv[tid];
                pos++;
            }
            if (s_s[e] == tid) s += s_dinv[tid] * s_dinv[s_d[e]];
        }
        g_acol[tid] = s / (float)NJ;
    }
    for (int idx = tid; idx < FD*4; idx += blockDim.x) {
        int k = idx >> 2, l = idx & 3;
        float s = 0.f;
        for (int c = 0; c < FD; ++c) s += wh[k*FD + c] * wc[c*4 + l];
        g_whc[idx] = s;
    }
    if (tid < 4) {
        float s = 0.f;
        for (int c = 0; c < FD; ++c) s += bh[c] * wc[c*4 + tid];
        g_bhc[tid] = s + bc[tid];
    }
}

// W[k][n] fp32 -> fragment-ordered bf16 hi/lo pack.
__global__ void convw_kernel(const float* __restrict__ W, int layer) {
    const int i = blockIdx.x * 256 + threadIdx.x;       // 0..16383
    const int lane = i & 31;
    const int ks = (i >> 5) & 15;
    const int nf = i >> 9;
    const int n = nf*8 + (lane >> 2);
    const int k = ks*16 + (lane & 3)*2;
    float e0 = W[k*FD + n],     e1 = W[(k+1)*FD + n];
    float e2 = W[(k+8)*FD + n], e3 = W[(k+9)*FD + n];
    __nv_bfloat162 h0 = __floats2bfloat162_rn(e0, e1);
    __nv_bfloat162 h1 = __floats2bfloat162_rn(e2, e3);
    __nv_bfloat162 l0 = __floats2bfloat162_rn(e0 - __low2float(h0), e1 - __high2float(h0));
    __nv_bfloat162 l1 = __floats2bfloat162_rn(e2 - __low2float(h1), e3 - __high2float(h1));
    g_wb_hi[layer][i] = (u64)(*(u32*)&h0) | ((u64)(*(u32*)&h1) << 32);
    g_wb_lo[layer][i] = (u64)(*(u32*)&l0) | ((u64)(*(u32*)&l1) << 32);
}

// ============================================================
// Fully fused layer: pre(Z) @ W  then  A_hat @ Y + b, BN sums.
// SMALL TILE for 2 blocks/SM (cross-block phase overlap):
// block = 2 graphs = 66 rows (pad 80 = 5 m16 tiles), 256 threads,
// 8 warps = 1m x 8n (warp n-stripe 32 cols). ~85.5KB smem.
// ============================================================
#define ASTRIDE 272
#define A_HI 0
#define A_LO 21760          /* 80*272 */
#define SM_SC 81920         /* ybuf [0, 81920) = 80 rows * 1KB */
#define SM_SH 82944
#define SM_RP 83968
#define SM_CI 84128
#define SM_AV 84792
#define FUSED_SMEM 85504

__device__ __forceinline__ void mma16816(float* d, u32 a0, u32 a1, u32 a2, u32 a3,
                                         u32 b0, u32 b1) {
    asm volatile(
        "mma.sync.aligned.m16n8k16.row.col.f32.bf16.bf16.f32 "
        "{%0,%1,%2,%3}, {%4,%5,%6,%7}, {%8,%9}, {%0,%1,%2,%3};"
        : "+f"(d[0]), "+f"(d[1]), "+f"(d[2]), "+f"(d[3])
        : "r"(a0), "r"(a1), "r"(a2), "r"(a3), "r"(b0), "r"(b1));
}

__global__ void __launch_bounds__(256, 2)
fused_kernel(const float* __restrict__ x_ext, const float* __restrict__ bias,
             int in_sel /*0 = x + nan_to_num, 1 = g_bufA + BN+relu*/,
             int layer, int Bn) {
    extern __shared__ char smem[];
    const int tid  = threadIdx.x;
    const int lane = tid & 31, wid = tid >> 5;     // 8 warps
    const int wn   = wid;                           // n stripe: cols [wn*32, wn*32+32)
    const int blk  = blockIdx.x;
    const int m0   = blk * 66;                      // global row base (graph-major, 2 graphs)
    const int NNv  = Bn * NJ;
    const int mode = in_sel;

    const float* in = (in_sel == 0) ? x_ext : (const float*)g_bufA;

    // stage BN params + CSR into smem (regions above ybuf; persist whole kernel)
    if (tid < 256) {
        *(float*)(smem + SM_SC + tid*4) = g_scale[tid];
        *(float*)(smem + SM_SH + tid*4) = g_shift[tid];
    }
    if (tid <= NJ) *(int*)(smem + SM_RP + tid*4) = g_rp[tid];
    if (tid < MAXE) {
        *(int*)  (smem + SM_CI + tid*4) = g_ci[tid];
        *(float*)(smem + SM_AV + tid*4) = g_av[tid];
    }

    float acc[5][4][4];
    #pragma unroll
    for (int mi = 0; mi < 5; ++mi)
        #pragma unroll
        for (int nf = 0; nf < 4; ++nf)
            #pragma unroll
            for (int q = 0; q < 4; ++q) acc[mi][nf][q] = 0.f;

    const u64* __restrict__ WBH = g_wb_hi[layer];
    const u64* __restrict__ WBL = g_wb_lo[layer];

    const float* ssc = (const float*)(smem + SM_SC);
    const float* ssh = (const float*)(smem + SM_SH);

    // ldmatrix lane address base: row = lane&15, k-half = lane>>4
    const u32 sbase = smem_u32(smem);
    const u32 lmbase = sbase + (u32)(((lane & 15))*ASTRIDE + (lane >> 4)*16);

    for (int c = 0; c < 2; ++c) {
        __syncthreads();
        // ---- stage A: 80 rows (66 valid) x 128 k; 2560 float4-slots, 10/thread ----
        #pragma unroll
        for (int it = 0; it < 10; ++it) {
            const int slot = tid + it*256;          // 0..2559
            const int r = slot >> 5, q4 = slot & 31;
            const int k = c*128 + q4*4;
            const bool ok = (r < 66) && (m0 + r < NNv);
            float4 v = make_float4(0.f, 0.f, 0.f, 0.f);
            if (ok) {
                v = *(const float4*)(in + (size_t)(m0 + r) * FD + k);
                if (mode == 0) {
                    if (v.x != v.x) v.x = 0.f;
                    if (v.y != v.y) v.y = 0.f;
                    if (v.z != v.z) v.z = 0.f;
                    if (v.w != v.w) v.w = 0.f;
                } else {
                    v.x = fmaxf(fmaf(v.x, ssc[k],   ssh[k]),   0.f);
                    v.y = fmaxf(fmaf(v.y, ssc[k+1], ssh[k+1]), 0.f);
                    v.z = fmaxf(fmaf(v.z, ssc[k+2], ssh[k+2]), 0.f);
                    v.w = fmaxf(fmaf(v.w, ssc[k+3], ssh[k+3]), 0.f);
                }
            }
            __nv_bfloat162 h0 = __floats2bfloat162_rn(v.x, v.y);
            __nv_bfloat162 h1 = __floats2bfloat162_rn(v.z, v.w);
            __nv_bfloat162 l0 = __floats2bfloat162_rn(v.x - __low2float(h0), v.y - __high2float(h0));
            __nv_bfloat162 l1 = __floats2bfloat162_rn(v.z - __low2float(h1), v.w - __high2float(h1));
            char* hib = smem + A_HI + r*ASTRIDE + q4*8;
            char* lob = smem + A_LO + r*ASTRIDE + q4*8;
            *(u32*)(hib)     = *(u32*)&h0;
            *(u32*)(hib + 4) = *(u32*)&h1;
            *(u32*)(lob)     = *(u32*)&l0;
            *(u32*)(lob + 4) = *(u32*)&l1;
        }
        __syncthreads();

        for (int ks = 0; ks < 8; ++ks) {
            const int ksa = c*8 + ks;
            // B fragments (L2-resident LDG.64, warp-coalesced)
            u64 vh[4], vl[4];
            #pragma unroll
            for (int nf = 0; nf < 4; ++nf) {
                const int idx = ((wn*4 + nf)*16 + ksa)*32 + lane;
                vh[nf] = WBH[idx];
                vl[nf] = WBL[idx];
            }
            const u32 kadd = (u32)(ks*32);
            // m-tiles in pairs: (0,1), (2,3), (4)
            #pragma unroll
            for (int mp = 0; mp < 3; ++mp) {
                const int mA = 2*mp, mB = 2*mp + 1;
                const bool hB = (mB < 5);
                u32 AH0[4], AL0[4], AH1[4], AL1[4];
                {
                    const u32 a0 = lmbase + (u32)(mA*16*ASTRIDE) + kadd;
                    ldsm_x4(AH0, a0);
                    ldsm_x4(AL0, a0 + (u32)A_LO);
                }
                if (hB) {
                    const u32 a1 = lmbase + (u32)(mB*16*ASTRIDE) + kadd;
                    ldsm_x4(AH1, a1);
                    ldsm_x4(AL1, a1 + (u32)A_LO);
                }
                // term 1: hi * b_hi
                #pragma unroll
                for (int nf = 0; nf < 4; ++nf)
                    mma16816(acc[mA][nf], AH0[0], AH0[1], AH0[2], AH0[3], (u32)vh[nf], (u32)(vh[nf] >> 32));
                if (hB) {
                    #pragma unroll
                    for (int nf = 0; nf < 4; ++nf)
                        mma16816(acc[mB][nf], AH1[0], AH1[1], AH1[2], AH1[3], (u32)vh[nf], (u32)(vh[nf] >> 32));
                }
                // term 2: hi * b_lo
                #pragma unroll
                for (int nf = 0; nf < 4; ++nf)
                    mma16816(acc[mA][nf], AH0[0], AH0[1], AH0[2], AH0[3], (u32)vl[nf], (u32)(vl[nf] >> 32));
                if (hB) {
                    #pragma unroll
                    for (int nf = 0; nf < 4; ++nf)
                        mma16816(acc[mB][nf], AH1[0], AH1[1], AH1[2], AH1[3], (u32)vl[nf], (u32)(vl[nf] >> 32));
                }
                // term 3: lo * b_hi
                #pragma unroll
                for (int nf = 0; nf < 4; ++nf)
                    mma16816(acc[mA][nf], AL0[0], AL0[1], AL0[2], AL0[3], (u32)vh[nf], (u32)(vh[nf] >> 32));
                if (hB) {
                    #pragma unroll
                    for (int nf = 0; nf < 4; ++nf)
                        mma16816(acc[mB][nf], AL1[0], AL1[1], AL1[2], AL1[3], (u32)vh[nf], (u32)(vh[nf] >> 32));
                }
            }
        }
    }

    // ---- stage Y into smem (overwrites A region) ----
    __syncthreads();
    float2* yb = (float2*)smem;                     // [row*128 + colpair], 80 rows
    const int arowb = (lane >> 2);
    const int cpb = wn*16 + (lane & 3);
    #pragma unroll
    for (int mi = 0; mi < 5; ++mi) {
        const int r0 = mi*16 + arowb;
        #pragma unroll
        for (int nf = 0; nf < 4; ++nf) {
            const int cpi = cpb + nf*4;
            yb[ r0     *128 + cpi] = make_float2(acc[mi][nf][0], acc[mi][nf][1]);
            yb[(r0 + 8)*128 + cpi] = make_float2(acc[mi][nf][2], acc[mi][nf][3]);
        }
    }
    __syncthreads();

    // ---- sparse A_hat epilogue + bias + BN sums ----
    const int cp = tid & 127, gi = tid >> 7;        // 2 graphs, 128 col-pairs
    const int g0 = blk*2 + gi;
    if (g0 < Bn) {
        const int*   srp = (const int*)(smem + SM_RP);
        const int*   sci = (const int*)(smem + SM_CI);
        const float* sav = (const float*)(smem + SM_AV);
        const float2 bia = ((const float2*)bias)[cp];
        float s1x = 0.f, s1y = 0.f, s2x = 0.f, s2y = 0.f;
        float* outg = g_bufA + (size_t)(m0 + gi*NJ) * FD;
        for (int j = 0; j < NJ; ++j) {
            float zx = bia.x, zy = bia.y;
            const int p1 = srp[j+1];
            for (int p = srp[j]; p < p1; ++p) {
                const float  a = sav[p];
                const float2 y = yb[(gi*NJ + sci[p])*128 + cp];
                zx = fmaf(a, y.x, zx);
                zy = fmaf(a, y.y, zy);
            }
            *(float2*)(outg + j*FD + cp*2) = make_float2(zx, zy);
            s1x += zx; s1y += zy;
            s2x = fmaf(zx, zx, s2x); s2y = fmaf(zy, zy, s2y);
        }
        atomicAdd(&g_sum[2*cp],     s1x);
        atomicAdd(&g_sum[2*cp + 1], s1y);
        atomicAdd(&g_sumsq[2*cp],     s2x);
        atomicAdd(&g_sumsq[2*cp + 1], s2y);
    }
}

// ============================================================
__global__ void stats_kernel(const float* __restrict__ g, const float* __restrict__ be,
                             float inv_nn) {
    int tid = threadIdx.x;
    float mu  = g_sum[tid] * inv_nn;
    float var = g_sumsq[tid] * inv_nn - mu * mu;
    float rs  = rsqrtf(var + 1e-5f);
    float sc  = rs * g[tid];
    g_scale[tid] = sc;
    g_shift[tid] = be[tid] - mu * sc;
    g_sum[tid] = 0.f; g_sumsq[tid] = 0.f;
}

// ============================================================
// Head: BN2+ReLU -> a_col^T h (per graph, graph-major) -> whc + bhc
// ============================================================
__global__ void __launch_bounds__(256)
final_kernel(float* __restrict__ out, int Bn) {
    __shared__ float s_acol[NJ];
    __shared__ float s_red[8][4];
    const int tid = threadIdx.x;
    const int b   = blockIdx.x;
    if (tid < NJ) s_acol[tid] = g_acol[tid];
    __syncthreads();

    const float sc  = g_scale[tid];
    const float shf = g_shift[tid];
    const float* inb = g_bufA + (size_t)b * NJ * FD;

    float v = 0.f;
    #pragma unroll
    for (int r = 0; r < NJ; ++r) {
        float x = inb[r*FD + tid];
        x = fmaxf(fmaf(x, sc, shf), 0.f);
        v = fmaf(s_acol[r], x, v);
    }
    float4 w = ((const float4*)g_whc)[tid];
    float p0 = v * w.x, p1 = v * w.y, p2 = v * w.z, p3 = v * w.w;
    #pragma unroll
    for (int o = 16; o; o >>= 1) {
        p0 += __shfl_down_sync(0xffffffffu, p0, o);
        p1 += __shfl_down_sync(0xffffffffu, p1, o);
        p2 += __shfl_down_sync(0xffffffffu, p2, o);
        p3 += __shfl_down_sync(0xffffffffu, p3, o);
    }
    const int lane = tid & 31, wid = tid >> 5;
    if (lane == 0) { s_red[wid][0] = p0; s_red[wid][1] = p1; s_red[wid][2] = p2; s_red[wid][3] = p3; }
    __syncthreads();
    if (tid < 4) {
        float s = 0.f;
        #pragma unroll
        for (int w8 = 0; w8 < 8; ++w8) s += s_red[w8][tid];
        out[b*4 + tid] = s + g_bhc[tid];
    }
}

// ============================================================
extern "C" void kernel_launch(void* const* d_in, const int* in_sizes, int n_in,
                              void* d_out, int out_size) {
    const float* x   = (const float*)d_in[0];
    const float* w0  = (const float*)d_in[1];
    const float* b0  = (const float*)d_in[2];
    const float* gg0 = (const float*)d_in[3];
    const float* be0 = (const float*)d_in[4];
    const float* w1  = (const float*)d_in[5];
    const float* b1  = (const float*)d_in[6];
    const float* gg1 = (const float*)d_in[7];
    const float* be1 = (const float*)d_in[8];
    const float* w2  = (const float*)d_in[9];
    const float* b2  = (const float*)d_in[10];
    const float* gg2 = (const float*)d_in[11];
    const float* be2 = (const float*)d_in[12];
    const float* wh  = (const float*)d_in[13];
    const float* bh  = (const float*)d_in[14];
    const float* wc  = (const float*)d_in[15];
    const float* bc  = (const float*)d_in[16];
    const int*   src = (const int*)d_in[17];
    const int*   dst = (const int*)d_in[18];
    float* out = (float*)d_out;

    const int B   = in_sizes[0] / (NJ * FD);
    const int epg = in_sizes[17] / B;
    const float inv_nn = 1.0f / (float)(B * NJ);
    const int fused_grid = (B + 1) / 2;

    static int smem_set = 0;
    if (!smem_set) {
        cudaFuncSetAttribute(fused_kernel, cudaFuncAttributeMaxDynamicSharedMemorySize, FUSED_SMEM);
        smem_set = 1;
    }

    // fused_kernel is launch #4 (ncu capture slot).
    prep_kernel<<<1, 256>>>(src, dst, epg, wh, wc, bh, bc);
    convw_kernel<<<64, 256>>>(w0, 0);
    convw_kernel<<<64, 256>>>(w1, 1);

    fused_kernel<<<fused_grid, 256, FUSED_SMEM>>>(x, b0, 0, 0, B);
    stats_kernel<<<1, 256>>>(gg0, be0, inv_nn);
    convw_kernel<<<64, 256>>>(w2, 2);

    fused_kernel<<<fused_grid, 256, FUSED_SMEM>>>(x, b1, 1, 1, B);
    stats_kernel<<<1, 256>>>(gg1, be1, inv_nn);

    fused_kernel<<<fused_grid, 256, FUSED_SMEM>>>(x, b2, 1, 2, B);
    stats_kernel<<<1, 256>>>(gg2, be2, inv_nn);

    final_kernel<<<B, 256>>>(out, B);
}